// round 6
// baseline (speedup 1.0000x reference)
#include <cuda_runtime.h>
#include <math.h>

#define NBATCH 8
#define DPIX   147456     // 384*384
#define KBINS  256
#define BINS   50
#define B_ROW  258        // odd-parity array row stride (even, keeps 8B align)
#define B_TOT  (NBATCH*KBINS*B_ROW + 4)   // divisible by 4

// Scratch (device globals; no dynamic allocation allowed)
__device__ __align__(16) float g_A[NBATCH * KBINS * KBINS];  // even-j0 histogram (2 MB)
__device__ __align__(16) float g_Braw[B_TOT];                // odd-j0 histogram (+1 float offset)
__device__ __align__(16) float g_G [BINS * KBINS];           // G[b][i]
__device__ __align__(16) float g_GT[KBINS * BINS];           // GT[i][b]
__device__ __align__(16) float g_P [2 * NBATCH * BINS * KBINS];  // P halves [is][n][b][j]
__device__ __align__(16) float g_hgram[NBATCH * BINS * BINS];
__device__ float g_mx[NBATCH * BINS];   // row marginals
__device__ float g_my[NBATCH * BINS];   // col marginals (atomic-accumulated)
__device__ float g_S;                   // grand total    (atomic-accumulated)

// ---------------- Kernel 1: zero scratch + precompute soft-bin kernel G -------
__global__ void k_init(float* __restrict__ out) {
    int gid = blockIdx.x * blockDim.x + threadIdx.x;
    int stride = gridDim.x * blockDim.x;
    if (gid == 0) { g_S = 0.0f; out[0] = 0.0f; }
    if (gid < NBATCH * BINS) g_my[gid] = 0.0f;

    float4 z = make_float4(0.f, 0.f, 0.f, 0.f);
    float4* A4 = (float4*)g_A;
    int totA = (NBATCH * KBINS * KBINS) / 4;
    for (int t = gid; t < totA; t += stride) A4[t] = z;
    float4* B4 = (float4*)g_Braw;
    int totB = B_TOT / 4;
    for (int t = gid; t < totB; t += stride) B4[t] = z;

    for (int t = gid; t < BINS * KBINS; t += stride) {
        int b = t / KBINS, i = t % KBINS;
        double x = (i + 0.5) / (double)KBINS;
        double c = (b + 0.5) * 0.02;
        double d = 10.0 * (x - c);
        double s1 = 1.0 / (1.0 + exp(-(d + 0.1)));
        double s2 = 1.0 / (1.0 + exp(-(d - 0.1)));
        float v = (float)(s1 - s2);
        g_G [b * KBINS + i] = v;
        g_GT[i * BINS  + b] = v;
    }
}

// ---------------- Kernel 2: bilinear 2D histogram with vector REDs ------------
__device__ __forceinline__ void red2(float* p, float a, float b) {
    asm volatile("red.global.add.v2.f32 [%0], {%1, %2};"
                 :: "l"(p), "f"(a), "f"(b) : "memory");
}

__global__ void k_hist(const float* __restrict__ im1, const float* __restrict__ im2) {
    int gid = blockIdx.x * blockDim.x + threadIdx.x;   // one float4 chunk (4 pixels)
    const int nchunk = (NBATCH * DPIX) / 4;
    if (gid >= nchunk) return;
    int n = gid / (DPIX / 4);   // 36864 chunks per batch, no straddle
    float4 xv = ((const float4*)im1)[gid];
    float4 yv = ((const float4*)im2)[gid];
    size_t baseA = (size_t)n * KBINS * KBINS;
    size_t baseB = (size_t)n * KBINS * B_ROW;

    float xs[4] = {xv.x, xv.y, xv.z, xv.w};
    float ys[4] = {yv.x, yv.y, yv.z, yv.w};
#pragma unroll
    for (int q = 0; q < 4; q++) {
        float u = xs[q] * 256.0f - 0.5f;
        float fi = fminf(254.0f, fmaxf(0.0f, floorf(u)));
        int   i0 = (int)fi;
        float wx = u - fi;
        float v  = ys[q] * 256.0f - 0.5f;
        float fj = fminf(254.0f, fmaxf(0.0f, floorf(v)));
        int   j0 = (int)fj;
        float wy = v - fj;
        float ax = 1.0f - wx, ay = 1.0f - wy;

        bool odd = (j0 & 1);
        float* arr = odd ? (g_Braw + 1 + baseB) : (g_A + baseA);
        int    rs  = odd ? B_ROW : KBINS;
        float* p   = arr + (size_t)i0 * rs + j0;   // 8B-aligned by parity construction
        red2(p,      ax * ay, ax * wy);
        red2(p + rs, wx * ay, wx * wy);
    }
}

// ---------------- Kernel 3: P[is][n][b][j] = sum_{i in half} G[b][i]*H[n][i][j]
// grid = 160 blocks, 128 threads
__global__ void k_stageC() {
    int blk = blockIdx.x;
    int n  = blk / 20;
    int r  = blk % 20;
    int jt = r / 10;
    int r2 = r % 10;
    int bg = r2 / 2, is = r2 % 2;
    int j  = jt * 128 + threadIdx.x;
    int b0 = bg * 10;
    int i_beg = is * 128;

    __shared__ float Gs[64][12];   // 48B rows -> float4-aligned
    float acc[10];
#pragma unroll
    for (int k = 0; k < 10; k++) acc[k] = 0.0f;

    const float* A = g_A    +      (size_t)n * KBINS * KBINS + j;
    const float* B = g_Braw + 1 +  (size_t)n * KBINS * B_ROW + j;

    for (int it = i_beg; it < i_beg + 128; it += 64) {
        __syncthreads();
        for (int t = threadIdx.x; t < 640; t += 128) {
            int ii = t / 10, k = t % 10;
            Gs[ii][k] = g_GT[(it + ii) * BINS + b0 + k];
        }
        __syncthreads();
#pragma unroll 8
        for (int ii = 0; ii < 64; ii++) {
            int i = it + ii;
            float h = A[(size_t)i * KBINS] + B[(size_t)i * B_ROW];
            float4 ga = *(const float4*)&Gs[ii][0];
            float4 gb = *(const float4*)&Gs[ii][4];
            float2 gc = *(const float2*)&Gs[ii][8];
            acc[0] += h * ga.x; acc[1] += h * ga.y; acc[2] += h * ga.z; acc[3] += h * ga.w;
            acc[4] += h * gb.x; acc[5] += h * gb.y; acc[6] += h * gb.z; acc[7] += h * gb.w;
            acc[8] += h * gc.x; acc[9] += h * gc.y;
        }
    }
    size_t pb = (((size_t)is * NBATCH + n) * BINS + b0) * KBINS + j;
#pragma unroll
    for (int k = 0; k < 10; k++) g_P[pb + (size_t)k * KBINS] = acc[k];
}

// ---------------- Kernel 4: hgram rows + marginals + total --------------------
// grid = 50 blocks (8 nb rows each), 512 threads: tid = r*64 + c
__global__ void __launch_bounds__(512) k_stageD() {
    __shared__ float Ps[8][KBINS];
    __shared__ float mxs[8];
    int tid = threadIdx.x;
    int r = tid >> 6, c = tid & 63;
    int nb0 = blockIdx.x * 8;

    if (tid < 8) mxs[tid] = 0.0f;

    // stage P rows (P0 + P1) into smem: 2048 elements, 4 per thread
    for (int t = tid; t < 8 * KBINS; t += 512) {
        int rr = t >> 8, j = t & 255;
        int nb = nb0 + rr;
        Ps[rr][j] = g_P[(size_t)nb * KBINS + j]
                  + g_P[(size_t)(NBATCH * BINS + nb) * KBINS + j];
    }
    __syncthreads();

    if (c < BINS) {
        int nb = nb0 + r;
        int n  = nb / BINS;
        const float* Pr = Ps[r];
        float a0 = 0.f, a1 = 0.f, a2 = 0.f, a3 = 0.f;
#pragma unroll 8
        for (int j = 0; j < KBINS; j += 4) {
            a0 += Pr[j]     * g_GT[(j)     * BINS + c];
            a1 += Pr[j + 1] * g_GT[(j + 1) * BINS + c];
            a2 += Pr[j + 2] * g_GT[(j + 2) * BINS + c];
            a3 += Pr[j + 3] * g_GT[(j + 3) * BINS + c];
        }
        float s = (a0 + a1) + (a2 + a3);
        g_hgram[(size_t)nb * BINS + c] = s;
        atomicAdd(&mxs[r], s);                    // smem row accumulation
        atomicAdd(&g_my[n * BINS + c], s);        // spread global REDs
    }
    __syncthreads();
    if (tid < 8) {
        g_mx[nb0 + tid] = mxs[tid];
        atomicAdd(&g_S, mxs[tid]);
    }
}

// ---------------- Kernel 5: MI terms, distributed ------------------------------
// grid = 400 (nb), 64 threads
__global__ void __launch_bounds__(64) k_stageE(float* __restrict__ out) {
    int nb = blockIdx.x;
    int n  = nb / BINS;
    int c  = threadIdx.x;
    float inv = 1.0f / g_S;
    float mi = 0.0f;
    if (c < BINS) {
        float p = g_hgram[(size_t)nb * BINS + c] * inv;
        float q = (g_mx[nb] * inv) * (g_my[n * BINS + c] * inv);
        mi = p * __logf(__fdividef(p + 1e-8f, q + 1e-8f));
    }
#pragma unroll
    for (int o = 16; o; o >>= 1) mi += __shfl_xor_sync(0xffffffffu, mi, o);
    __shared__ float wsum[2];
    if ((threadIdx.x & 31) == 0) wsum[threadIdx.x >> 5] = mi;
    __syncthreads();
    if (threadIdx.x == 0) atomicAdd(out, wsum[0] + wsum[1]);
}

// ---------------- Launch -------------------------------------------------------
extern "C" void kernel_launch(void* const* d_in, const int* in_sizes, int n_in,
                              void* d_out, int out_size) {
    const float* im1 = (const float*)d_in[0];
    const float* im2 = (const float*)d_in[1];
    k_init  <<<512, 256>>>((float*)d_out);
    k_hist  <<<(NBATCH * DPIX / 4 + 255) / 256, 256>>>(im1, im2);
    k_stageC<<<160, 128>>>();
    k_stageD<<<50, 512>>>();
    k_stageE<<<400, 64>>>((float*)d_out);
}

// round 7
// speedup vs baseline: 1.3628x; 1.3628x over previous
#include <cuda_runtime.h>
#include <math.h>

#define NBATCH 8
#define DPIX   147456     // 384*384
#define KBINS  256
#define BINS   50

// Scratch (device globals; no dynamic allocation allowed)
__device__ __align__(16) float g_A[NBATCH * KBINS * KBINS];  // fine 2D histogram (2 MB)
__device__ __align__(16) float g_G [BINS * KBINS];           // G[b][i]
__device__ __align__(16) float g_GT[KBINS * BINS];           // GT[i][b]
__device__ __align__(16) float g_P [2 * NBATCH * BINS * KBINS];  // P halves [is][n][b][j]
__device__ __align__(16) float g_hgram[NBATCH * BINS * BINS];
__device__ float g_mx[NBATCH * BINS];   // row marginals
__device__ float g_my[NBATCH * BINS];   // col marginals (atomic-accumulated)
__device__ float g_S;                   // grand total    (atomic-accumulated)

// ---------------- Kernel 1: zero scratch + precompute soft-bin kernel G -------
__global__ void k_init(float* __restrict__ out) {
    int gid = blockIdx.x * blockDim.x + threadIdx.x;
    int stride = gridDim.x * blockDim.x;
    if (gid == 0) { g_S = 0.0f; out[0] = 0.0f; }
    if (gid < NBATCH * BINS) g_my[gid] = 0.0f;

    float4 z = make_float4(0.f, 0.f, 0.f, 0.f);
    float4* A4 = (float4*)g_A;
    int totA = (NBATCH * KBINS * KBINS) / 4;
    for (int t = gid; t < totA; t += stride) A4[t] = z;

    for (int t = gid; t < BINS * KBINS; t += stride) {
        int b = t / KBINS, i = t % KBINS;
        double x = (i + 0.5) / (double)KBINS;
        double c = (b + 0.5) * 0.02;
        double d = 10.0 * (x - c);
        double s1 = 1.0 / (1.0 + exp(-(d + 0.1)));
        double s2 = 1.0 / (1.0 + exp(-(d - 0.1)));
        float v = (float)(s1 - s2);
        g_G [b * KBINS + i] = v;
        g_GT[i * BINS  + b] = v;
    }
}

// ---------------- Kernel 2: nearest-cell 2D histogram (1 scalar RED / pixel) --
__device__ __forceinline__ void red1(float* p, float a) {
    asm volatile("red.global.add.f32 [%0], %1;" :: "l"(p), "f"(a) : "memory");
}

__global__ void k_hist(const float* __restrict__ im1, const float* __restrict__ im2) {
    int gid = blockIdx.x * blockDim.x + threadIdx.x;   // one float4 chunk (4 pixels)
    const int nchunk = (NBATCH * DPIX) / 4;
    if (gid >= nchunk) return;
    int n = gid / (DPIX / 4);   // 36864 chunks per batch, no straddle
    float4 xv = ((const float4*)im1)[gid];
    float4 yv = ((const float4*)im2)[gid];
    float* base = g_A + (size_t)n * KBINS * KBINS;

    float xs[4] = {xv.x, xv.y, xv.z, xv.w};
    float ys[4] = {yv.x, yv.y, yv.z, yv.w};
#pragma unroll
    for (int q = 0; q < 4; q++) {
        int i0 = min(KBINS - 1, (int)(xs[q] * 256.0f));
        int j0 = min(KBINS - 1, (int)(ys[q] * 256.0f));
        red1(base + i0 * KBINS + j0, 1.0f);
    }
}

// ---------------- Kernel 3: P[is][n][b][j] = sum_{i in half} G[b][i]*H[n][i][j]
// grid = 160 blocks, 128 threads
__global__ void k_stageC() {
    int blk = blockIdx.x;
    int n  = blk / 20;
    int r  = blk % 20;
    int jt = r / 10;
    int r2 = r % 10;
    int bg = r2 / 2, is = r2 % 2;
    int j  = jt * 128 + threadIdx.x;
    int b0 = bg * 10;
    int i_beg = is * 128;

    __shared__ float Gs[64][12];   // 48B rows -> float4-aligned
    float acc[10];
#pragma unroll
    for (int k = 0; k < 10; k++) acc[k] = 0.0f;

    const float* A = g_A + (size_t)n * KBINS * KBINS + j;

    for (int it = i_beg; it < i_beg + 128; it += 64) {
        __syncthreads();
        for (int t = threadIdx.x; t < 640; t += 128) {
            int ii = t / 10, k = t % 10;
            Gs[ii][k] = g_GT[(it + ii) * BINS + b0 + k];
        }
        __syncthreads();
#pragma unroll 8
        for (int ii = 0; ii < 64; ii++) {
            int i = it + ii;
            float h = A[(size_t)i * KBINS];
            float4 ga = *(const float4*)&Gs[ii][0];
            float4 gb = *(const float4*)&Gs[ii][4];
            float2 gc = *(const float2*)&Gs[ii][8];
            acc[0] += h * ga.x; acc[1] += h * ga.y; acc[2] += h * ga.z; acc[3] += h * ga.w;
            acc[4] += h * gb.x; acc[5] += h * gb.y; acc[6] += h * gb.z; acc[7] += h * gb.w;
            acc[8] += h * gc.x; acc[9] += h * gc.y;
        }
    }
    size_t pb = (((size_t)is * NBATCH + n) * BINS + b0) * KBINS + j;
#pragma unroll
    for (int k = 0; k < 10; k++) g_P[pb + (size_t)k * KBINS] = acc[k];
}

// ---------------- Kernel 4: hgram row + marginals + total ---------------------
// grid = 400 (nb = n*50+b), 256 threads  (R5 shape — measured 10.9us)
__global__ void k_stageD() {
    int nb = blockIdx.x;
    int n  = nb / BINS;
    __shared__ float Ps[KBINS];
    __shared__ float rows[BINS];
    const float* P0 = g_P + (size_t)nb * KBINS;
    const float* P1 = g_P + (size_t)(NBATCH * BINS + nb) * KBINS;
    for (int t = threadIdx.x; t < KBINS; t += 256) Ps[t] = P0[t] + P1[t];
    __syncthreads();
    int w = threadIdx.x >> 5, lane = threadIdx.x & 31;
    for (int c = w; c < BINS; c += 8) {
        const float* Gc = g_G + (size_t)c * KBINS;
        float s0 = 0.0f, s1 = 0.0f;
#pragma unroll
        for (int q = 0; q < KBINS / 64; q++) {
            int jj = q * 64 + lane;
            s0 += Ps[jj]      * Gc[jj];
            s1 += Ps[jj + 32] * Gc[jj + 32];
        }
        float s = s0 + s1;
#pragma unroll
        for (int o = 16; o; o >>= 1) s += __shfl_xor_sync(0xffffffffu, s, o);
        if (lane == 0) {
            g_hgram[(size_t)nb * BINS + c] = s;
            rows[c] = s;
            atomicAdd(&g_my[n * BINS + c], s);
        }
    }
    __syncthreads();
    if (threadIdx.x == 0) {
        float r = 0.0f;
#pragma unroll
        for (int c = 0; c < BINS; c++) r += rows[c];
        g_mx[nb] = r;
        atomicAdd(&g_S, r);
    }
}

// ---------------- Kernel 5: MI terms, distributed ------------------------------
// grid = 400 (nb), 64 threads
__global__ void __launch_bounds__(64) k_stageE(float* __restrict__ out) {
    int nb = blockIdx.x;
    int n  = nb / BINS;
    int c  = threadIdx.x;
    float inv = 1.0f / g_S;
    float mi = 0.0f;
    if (c < BINS) {
        float p = g_hgram[(size_t)nb * BINS + c] * inv;
        float q = (g_mx[nb] * inv) * (g_my[n * BINS + c] * inv);
        mi = p * __logf(__fdividef(p + 1e-8f, q + 1e-8f));
    }
#pragma unroll
    for (int o = 16; o; o >>= 1) mi += __shfl_xor_sync(0xffffffffu, mi, o);
    __shared__ float wsum[2];
    if ((threadIdx.x & 31) == 0) wsum[threadIdx.x >> 5] = mi;
    __syncthreads();
    if (threadIdx.x == 0) atomicAdd(out, wsum[0] + wsum[1]);
}

// ---------------- Launch -------------------------------------------------------
extern "C" void kernel_launch(void* const* d_in, const int* in_sizes, int n_in,
                              void* d_out, int out_size) {
    const float* im1 = (const float*)d_in[0];
    const float* im2 = (const float*)d_in[1];
    k_init  <<<512, 256>>>((float*)d_out);
    k_hist  <<<(NBATCH * DPIX / 4 + 255) / 256, 256>>>(im1, im2);
    k_stageC<<<160, 128>>>();
    k_stageD<<<400, 256>>>();
    k_stageE<<<400, 64>>>((float*)d_out);
}

// round 8
// speedup vs baseline: 1.4277x; 1.0476x over previous
#include <cuda_runtime.h>
#include <math.h>

#define NBATCH 8
#define DPIX   147456     // 384*384
#define KBINS  256
#define BINS   50

// Scratch (device globals; no dynamic allocation allowed)
__device__ __align__(16) float g_A[NBATCH * KBINS * KBINS];  // fine 2D histogram (2 MB)
__device__ __align__(16) float g_G [BINS * KBINS];           // G[b][i]
__device__ __align__(16) float g_GT[KBINS * BINS];           // GT[i][b]
__device__ __align__(16) float g_P [2 * NBATCH * BINS * KBINS];  // P halves [is][n][b][j]
__device__ __align__(16) float g_hgram[NBATCH * BINS * BINS];
__device__ float g_mx[NBATCH * BINS];   // row marginals
__device__ float g_my[NBATCH * BINS];   // col marginals (atomic-accumulated)
__device__ float g_S;                   // grand total    (atomic-accumulated)

// ---------------- Kernel 1: zero scratch + precompute soft-bin kernel G -------
__global__ void k_init(float* __restrict__ out) {
    int gid = blockIdx.x * blockDim.x + threadIdx.x;
    int stride = gridDim.x * blockDim.x;
    if (gid == 0) { g_S = 0.0f; out[0] = 0.0f; }
    if (gid < NBATCH * BINS) g_my[gid] = 0.0f;

    float4 z = make_float4(0.f, 0.f, 0.f, 0.f);
    float4* A4 = (float4*)g_A;
    int totA = (NBATCH * KBINS * KBINS) / 4;
    for (int t = gid; t < totA; t += stride) A4[t] = z;

    for (int t = gid; t < BINS * KBINS; t += stride) {
        int b = t / KBINS, i = t % KBINS;
        double x = (i + 0.5) / (double)KBINS;
        double c = (b + 0.5) * 0.02;
        double d = 10.0 * (x - c);
        double s1 = 1.0 / (1.0 + exp(-(d + 0.1)));
        double s2 = 1.0 / (1.0 + exp(-(d - 0.1)));
        float v = (float)(s1 - s2);
        g_G [b * KBINS + i] = v;
        g_GT[i * BINS  + b] = v;
    }
}

// ---------------- Kernel 2: nearest-cell 2D histogram (1 scalar RED / pixel) --
__device__ __forceinline__ void red1(float* p, float a) {
    asm volatile("red.global.add.f32 [%0], %1;" :: "l"(p), "f"(a) : "memory");
}

__global__ void k_hist(const float* __restrict__ im1, const float* __restrict__ im2) {
    int gid = blockIdx.x * blockDim.x + threadIdx.x;   // one float4 chunk (4 pixels)
    const int nchunk = (NBATCH * DPIX) / 4;
    if (gid >= nchunk) return;
    int n = gid / (DPIX / 4);   // 36864 chunks per batch, no straddle
    float4 xv = ((const float4*)im1)[gid];
    float4 yv = ((const float4*)im2)[gid];
    float* base = g_A + (size_t)n * KBINS * KBINS;

    float xs[4] = {xv.x, xv.y, xv.z, xv.w};
    float ys[4] = {yv.x, yv.y, yv.z, yv.w};
#pragma unroll
    for (int q = 0; q < 4; q++) {
        int i0 = min(KBINS - 1, (int)(xs[q] * 256.0f));
        int j0 = min(KBINS - 1, (int)(ys[q] * 256.0f));
        red1(base + i0 * KBINS + j0, 1.0f);
    }
}

// ---------------- Kernel 3: P[is][n][b][j] = sum_{i in half} G[b][i]*H[n][i][j]
// grid = 160 blocks, 128 threads
__global__ void k_stageC() {
    int blk = blockIdx.x;
    int n  = blk / 20;
    int r  = blk % 20;
    int jt = r / 10;
    int r2 = r % 10;
    int bg = r2 / 2, is = r2 % 2;
    int j  = jt * 128 + threadIdx.x;
    int b0 = bg * 10;
    int i_beg = is * 128;

    __shared__ float Gs[64][12];   // 48B rows -> float4-aligned
    float acc[10];
#pragma unroll
    for (int k = 0; k < 10; k++) acc[k] = 0.0f;

    const float* A = g_A + (size_t)n * KBINS * KBINS + j;

    for (int it = i_beg; it < i_beg + 128; it += 64) {
        __syncthreads();
        for (int t = threadIdx.x; t < 640; t += 128) {
            int ii = t / 10, k = t % 10;
            Gs[ii][k] = g_GT[(it + ii) * BINS + b0 + k];
        }
        __syncthreads();
#pragma unroll 8
        for (int ii = 0; ii < 64; ii++) {
            int i = it + ii;
            float h = A[(size_t)i * KBINS];
            float4 ga = *(const float4*)&Gs[ii][0];
            float4 gb = *(const float4*)&Gs[ii][4];
            float2 gc = *(const float2*)&Gs[ii][8];
            acc[0] += h * ga.x; acc[1] += h * ga.y; acc[2] += h * ga.z; acc[3] += h * ga.w;
            acc[4] += h * gb.x; acc[5] += h * gb.y; acc[6] += h * gb.z; acc[7] += h * gb.w;
            acc[8] += h * gc.x; acc[9] += h * gc.y;
        }
    }
    size_t pb = (((size_t)is * NBATCH + n) * BINS + b0) * KBINS + j;
#pragma unroll
    for (int k = 0; k < 10; k++) g_P[pb + (size_t)k * KBINS] = acc[k];
}

// ---------------- Kernel 4: hgram row + marginals + total ---------------------
// grid = 400 (nb = n*50+b), 64 threads, thread-per-c (no shuffles in hot path)
__global__ void __launch_bounds__(64) k_stageD() {
    int nb = blockIdx.x;
    int n  = nb / BINS;
    __shared__ float Ps[KBINS];
    __shared__ float rows[64];
    int tid = threadIdx.x;

    // stage Ps: 256 floats = 64 float4s, one per thread
    {
        const float4* P0 = (const float4*)(g_P + (size_t)nb * KBINS);
        const float4* P1 = (const float4*)(g_P + (size_t)(NBATCH * BINS + nb) * KBINS);
        float4 a = P0[tid], b = P1[tid];
        ((float4*)Ps)[tid] = make_float4(a.x + b.x, a.y + b.y, a.z + b.z, a.w + b.w);
    }
    __syncthreads();

    float s = 0.0f;
    int c = tid;
    if (c < BINS) {
        const float* GTc = g_GT + c;
        float a0 = 0.f, a1 = 0.f, a2 = 0.f, a3 = 0.f;
#pragma unroll 8
        for (int j = 0; j < KBINS; j += 4) {
            a0 += Ps[j]     * GTc[(j)     * BINS];
            a1 += Ps[j + 1] * GTc[(j + 1) * BINS];
            a2 += Ps[j + 2] * GTc[(j + 2) * BINS];
            a3 += Ps[j + 3] * GTc[(j + 3) * BINS];
        }
        s = (a0 + a1) + (a2 + a3);
        g_hgram[(size_t)nb * BINS + c] = s;
        atomicAdd(&g_my[n * BINS + c], s);    // spread global REDs
    }

    // row marginal: one reduction per block
    rows[tid] = s;
    __syncthreads();
    if (tid < 32) {
        float r = rows[tid] + rows[tid + 32];
#pragma unroll
        for (int o = 16; o; o >>= 1) r += __shfl_xor_sync(0xffffffffu, r, o);
        if (tid == 0) {
            g_mx[nb] = r;
            atomicAdd(&g_S, r);
        }
    }
}

// ---------------- Kernel 5: MI terms, distributed ------------------------------
// grid = 400 (nb), 64 threads
__global__ void __launch_bounds__(64) k_stageE(float* __restrict__ out) {
    int nb = blockIdx.x;
    int n  = nb / BINS;
    int c  = threadIdx.x;
    float inv = 1.0f / g_S;
    float mi = 0.0f;
    if (c < BINS) {
        float p = g_hgram[(size_t)nb * BINS + c] * inv;
        float q = (g_mx[nb] * inv) * (g_my[n * BINS + c] * inv);
        mi = p * __logf(__fdividef(p + 1e-8f, q + 1e-8f));
    }
#pragma unroll
    for (int o = 16; o; o >>= 1) mi += __shfl_xor_sync(0xffffffffu, mi, o);
    __shared__ float wsum[2];
    if ((threadIdx.x & 31) == 0) wsum[threadIdx.x >> 5] = mi;
    __syncthreads();
    if (threadIdx.x == 0) atomicAdd(out, wsum[0] + wsum[1]);
}

// ---------------- Launch -------------------------------------------------------
extern "C" void kernel_launch(void* const* d_in, const int* in_sizes, int n_in,
                              void* d_out, int out_size) {
    const float* im1 = (const float*)d_in[0];
    const float* im2 = (const float*)d_in[1];
    k_init  <<<512, 256>>>((float*)d_out);
    k_hist  <<<(NBATCH * DPIX / 4 + 255) / 256, 256>>>(im1, im2);
    k_stageC<<<160, 128>>>();
    k_stageD<<<400, 64>>>();
    k_stageE<<<400, 64>>>((float*)d_out);
}